// round 17
// baseline (speedup 1.0000x reference)
#include <cuda_runtime.h>
#include <math.h>

#define NC 10
#define NG 8
#define TPB 256
#define WARPS (TPB / 32)
#define QCAP 256           // gather index-ring capacity per warp (ints)
#define DQCAP 64           // stream data-ring capacity per warp (rows)
#define GCLS 8             // gathered classes: 0..7
#define BPC  59            // blocks per gathered class
#define SB   60            // blocks per streamed class (classes 8..9)
#define GRID (GCLS * BPC + (NC - GCLS) * SB)   // 592 = one wave @4/SM

// Scratch (__device__ globals; zero-init at load; finalize resets for replays)
__device__ float g_S[NC * NG];
__device__ float g_V[NC * NG];
__device__ float g_count[NC];
__device__ unsigned g_ticket;

// Accumulate one row held in float a[NG]:
//   S_i += a_i;  V_i += a_i * (R - log a_i),  R = sum_j log a_j
#define ACCA(A)                                                                 \
    {                                                                           \
        float la[NG]; float R = 0.0f;                                           \
        _Pragma("unroll")                                                       \
        for (int g = 0; g < NG; ++g) { la[g] = __logf((A)[g]); R += la[g]; }    \
        _Pragma("unroll")                                                       \
        for (int g = 0; g < NG; ++g) {                                          \
            s[g] += (A)[g];                                                     \
            v[g] = fmaf((A)[g], R - la[g], v[g]);                               \
        }                                                                       \
    }

// ---------------------------------------------------------------------------
// Hybrid kernel, both roles compute-compacted:
//  * Gather role (classes 0..GCLS-1): warp-compacted label scan + scattered
//    32B row gather (DRAM bank-activation-bound; bus mostly idle).
//  * Stream role (classes GCLS..NC-1): dense sequential line sweep (__ldcs,
//    evict-first) that ballot-compacts ONLY matched rows through a shared
//    data ring (9-float stride -> conflict-free) and processes them in full
//    32-lane batches. Sequential bytes ride the bus cycles the gather leaves
//    idle; compute per row identical to the gather role.
// Last-block ticket finalize.
__global__ __launch_bounds__(TPB, 4) void k_all(const float* __restrict__ act,
                                                const int* __restrict__ labels,
                                                int N, float* __restrict__ out) {
    const int w    = threadIdx.x >> 5;
    const int lane = threadIdx.x & 31;
    const int nq   = N >> 2;
    const int4* lab4 = (const int4*)labels;
    const unsigned ltmask = (1u << lane) - 1u;

    // per-warp pool: gather aliases it as int ring, stream as float data ring
    __shared__ float spool[WARPS][DQCAP * 9];
    __shared__ float sh[2 * NG + 1];
    __shared__ bool amLast;
    __shared__ float pc[NC];

    if (threadIdx.x < 2 * NG + 1) sh[threadIdx.x] = 0.0f;
    __syncthreads();

    float s[NG] = {0,0,0,0,0,0,0,0};
    float v[NG] = {0,0,0,0,0,0,0,0};
    float cnt = 0.0f;
    unsigned head = 0, tail = 0;   // warp-uniform ring cursors
    int c;

    if (blockIdx.x < GCLS * BPC) {
        // ================= GATHER ROLE =================
        c = blockIdx.x / BPC;
        const int b = blockIdx.x % BPC;
        const int want = c + 1;
        const size_t clsBase = (size_t)c * (size_t)N;
        int* qbuf = (int*)spool[w];
        const int gw     = b * WARPS + w;
        const int stride = BPC * WARPS * 32;

        #define BATCH32()                                                       \
            {                                                                   \
                __syncwarp();                                                   \
                int idx = qbuf[(head + lane) & (QCAP - 1)];                     \
                head += 32;                                                     \
                const float4* r = (const float4*)(act + (clsBase + (size_t)idx) * NG); \
                float4 aq = r[0], bq = r[1];                                    \
                float a[NG] = {aq.x, aq.y, aq.z, aq.w, bq.x, bq.y, bq.z, bq.w}; \
                ACCA(a)                                                         \
            }
        #define SLOT(LV, OFF)                                                  \
            {                                                                   \
                unsigned m = __ballot_sync(0xFFFFFFFFu, (LV) == want);          \
                if ((LV) == want)                                               \
                    qbuf[(tail + __popc(m & ltmask)) & (QCAP - 1)] = n + (OFF); \
                tail += __popc(m);                                              \
            }

        for (int base = gw * 32; base < nq; base += stride) {
            int q = base + lane;
            int4 lb;
            if (q < nq) lb = lab4[q];
            else        { lb.x = 0; lb.y = 0; lb.z = 0; lb.w = 0; }
            int n = q << 2;
            SLOT(lb.x, 0) SLOT(lb.y, 1) SLOT(lb.z, 2) SLOT(lb.w, 3)
            while (tail - head >= 32) BATCH32()
        }
        // scalar label tail (N % 4): block 0, warp 0 of this class
        if (b == 0 && w == 0) {
            for (int nb = nq << 2; nb < N; nb += 32) {
                int n = nb + lane;
                int lv = (n < N) ? labels[n] : 0;
                unsigned m = __ballot_sync(0xFFFFFFFFu, lv == want);
                if (lv == want)
                    qbuf[(tail + __popc(m & ltmask)) & (QCAP - 1)] = n;
                tail += __popc(m);
                while (tail - head >= 32) BATCH32()
            }
        }
        // drain the final <32 with predication
        {
            unsigned rem = tail - head;
            __syncwarp();
            int idx = (lane < (int)rem) ? qbuf[(head + lane) & (QCAP - 1)] : 0;
            if (lane < (int)rem) {
                const float4* r = (const float4*)(act + (clsBase + (size_t)idx) * NG);
                float4 aq = r[0], bq = r[1];
                float a[NG] = {aq.x, aq.y, aq.z, aq.w, bq.x, bq.y, bq.z, bq.w};
                ACCA(a)
            }
        }
        #undef SLOT
        #undef BATCH32
        cnt = (lane == 0) ? (float)tail : 0.0f;
    } else {
        // ================= STREAM ROLE =================
        const int sb = blockIdx.x - GCLS * BPC;
        c = GCLS + sb / SB;
        const int b = sb % SB;
        const int want = c + 1;
        const size_t clsBase = (size_t)c * (size_t)N;
        float* dpool = spool[w];
        const int gw     = b * WARPS + w;
        const int stride = SB * WARPS * 32;

        #define DBATCH32()                                                      \
            {                                                                   \
                __syncwarp();                                                   \
                const float* p = &dpool[((head + lane) & (DQCAP - 1)) * 9];     \
                head += 32;                                                     \
                float a[NG];                                                    \
                _Pragma("unroll")                                               \
                for (int g = 0; g < NG; ++g) a[g] = p[g];                       \
                ACCA(a)                                                         \
            }
        // dense-load row j, enqueue if matched; drain keeps ring <= DQCAP-1
        #define SSLOT(LV, J)                                                    \
            {                                                                   \
                float4 ra = make_float4(1, 1, 1, 1), rb = ra;                   \
                if (q < nq) { ra = __ldcs(L + 2 * (J)); rb = __ldcs(L + 2 * (J) + 1); } \
                unsigned m = __ballot_sync(0xFFFFFFFFu, (LV) == want);          \
                if ((LV) == want) {                                             \
                    float* p = &dpool[((tail + __popc(m & ltmask)) & (DQCAP - 1)) * 9]; \
                    p[0] = ra.x; p[1] = ra.y; p[2] = ra.z; p[3] = ra.w;         \
                    p[4] = rb.x; p[5] = rb.y; p[6] = rb.z; p[7] = rb.w;         \
                }                                                               \
                tail += __popc(m);                                              \
                while (tail - head >= 32) DBATCH32()                            \
            }

        for (int base = gw * 32; base < nq; base += stride) {
            int q = base + lane;
            int4 lb;
            if (q < nq) lb = lab4[q];
            else        { lb.x = 0; lb.y = 0; lb.z = 0; lb.w = 0; }
            const float4* L = (const float4*)(act + clsBase + ((size_t)q << 5));
            SSLOT(lb.x, 0) SSLOT(lb.y, 1) SSLOT(lb.z, 2) SSLOT(lb.w, 3)
        }
        // drain the final <32 with predication
        {
            unsigned rem = tail - head;
            __syncwarp();
            if (lane < (int)rem) {
                const float* p = &dpool[((head + lane) & (DQCAP - 1)) * 9];
                float a[NG];
                #pragma unroll
                for (int g = 0; g < NG; ++g) a[g] = p[g];
                ACCA(a)
            }
        }
        #undef SSLOT
        #undef DBATCH32
        cnt = (lane == 0) ? (float)tail : 0.0f;
        // scalar row tail (N % 4): block 0, warp 0, direct (matched-only)
        if (b == 0 && w == 0) {
            int n = (nq << 2) + lane;
            if (n < N && labels[n] == want) {
                const float4* r = (const float4*)(act + (clsBase + (size_t)n) * NG);
                float4 aq = r[0], bq = r[1];
                float a[NG] = {aq.x, aq.y, aq.z, aq.w, bq.x, bq.y, bq.z, bq.w};
                ACCA(a)
                cnt += 1.0f;
            }
        }
    }

    // ---- common epilogue: warp reduce 17 values, block reduce, global atomics
    #pragma unroll
    for (int o = 16; o > 0; o >>= 1) {
        #pragma unroll
        for (int g = 0; g < NG; ++g) {
            s[g] += __shfl_down_sync(0xFFFFFFFFu, s[g], o);
            v[g] += __shfl_down_sync(0xFFFFFFFFu, v[g], o);
        }
        cnt += __shfl_down_sync(0xFFFFFFFFu, cnt, o);
    }
    if (lane == 0) {
        #pragma unroll
        for (int g = 0; g < NG; ++g) {
            atomicAdd(&sh[g], s[g]);
            atomicAdd(&sh[NG + g], v[g]);
        }
        atomicAdd(&sh[2 * NG], cnt);
    }
    __syncthreads();
    if (threadIdx.x < NG) {
        atomicAdd(&g_S[c * NG + threadIdx.x], sh[threadIdx.x]);
        atomicAdd(&g_V[c * NG + threadIdx.x], sh[NG + threadIdx.x]);
    }
    if (threadIdx.x == 2 * NG) atomicAdd(&g_count[c], sh[2 * NG]);

    // ---- last-block finalize ----
    __threadfence();
    if (threadIdx.x == 0)
        amLast = (atomicAdd(&g_ticket, 1u) == (unsigned)(GRID - 1));
    __syncthreads();
    if (!amLast) return;

    int t = threadIdx.x;
    if (t < NC) pc[t] = 0.0f;
    __syncthreads();
    if (t < NC * NG) {
        float S = __ldcg(&g_S[t]);
        float V = __ldcg(&g_V[t]);
        float term = V / S - (float)(NG - 1) * logf(S);
        atomicAdd(&pc[t / NG], term);
    }
    __syncthreads();
    if (t == 0) {
        float num = 0.0f, vcnt = 0.0f;
        #pragma unroll
        for (int cc = 0; cc < NC; ++cc) {
            float cn = __ldcg(&g_count[cc]);
            if (cn >= 2.0f) { num += pc[cc]; vcnt += 1.0f; }
        }
        out[0] = num / (vcnt * (float)(NG * (NG - 1)));
        g_ticket = 0;                               // reset for next replay
    }
    __syncthreads();
    if (t < NC * NG) { g_S[t] = 0.0f; g_V[t] = 0.0f; }
    if (t < NC) g_count[t] = 0.0f;
}

// ---------------------------------------------------------------------------
extern "C" void kernel_launch(void* const* d_in, const int* in_sizes, int n_in,
                              void* d_out, int out_size) {
    const float* act  = (const float*)d_in[0];   // [C, N, G] float32
    const int* labels = (const int*)d_in[1];     // [N] int32
    const int N = in_sizes[1];

    k_all<<<GRID, TPB>>>(act, labels, N, (float*)d_out);
}